// round 12
// baseline (speedup 1.0000x reference)
#include <cuda_runtime.h>
#include <cstdint>

#define CIN 3
#define COUT 16
#define HH 32
#define WW 32
#define OH 30
#define OW 30

typedef unsigned long long u64;

// ---- f32x2 packed-math helpers (SASS FFMA2 via PTX only) ----
__device__ __forceinline__ u64 pk2(float a, float b) {
    u64 r; asm("mov.b64 %0, {%1, %2};" : "=l"(r) : "f"(a), "f"(b)); return r;
}
__device__ __forceinline__ u64 dup2(float a) {
    u64 r; asm("mov.b64 %0, {%1, %1};" : "=l"(r) : "f"(a)); return r;
}
__device__ __forceinline__ u64 fma2(u64 a, u64 b, u64 c) {
    u64 d; asm("fma.rn.f32x2 %0, %1, %2, %3;" : "=l"(d) : "l"(a), "l"(b), "l"(c)); return d;
}
__device__ __forceinline__ void upk2(u64 v, float& a, float& b) {
    asm("mov.b64 {%0, %1}, %2;" : "=f"(a), "=f"(b) : "l"(v));
}
// activation: relu(v) * min(v+3,6)/6 == max(v,0) * min(v/6+0.5, 1)
__device__ __forceinline__ float hswish_relu(float v) {
    return fmaxf(v, 0.0f) * fminf(fmaf(v, 1.0f / 6.0f, 0.5f), 1.0f);
}

// Direct conv v6 — column-pair packing.
// Grid 8192: block b -> image b>>1, channel-half b&1. 128 threads = 4 warps.
// Warp w -> channel pair; lane L -> channel c0+(L>>4), COLUMN PAIR k=L&15
// (acc f32x2 = {out[2k], out[2k+1]} of ONE channel). The input operand for
// tap kx is {x[2k+kx], x[2k+kx+1]}: kx=0 and kx=2 come directly from two
// aligned LDS.64 (no duplication!), only the middle pair needs one pack MOV.
// Weights are {w,w} duplicated once per lane at setup. Stores: one STG.64/row.
// Issue budget/row drops ~63 -> ~47 slots < 54 fma cyc -> fma-pipe-bound.
__global__ void __launch_bounds__(128, 5) conv3x3_hswish_kernel(
    const float* __restrict__ x,
    const float* __restrict__ wgt,
    const float* __restrict__ bias,
    float* __restrict__ out)
{
    __shared__ float s_in[CIN * HH * WW];   // 12 KB

    const int n    = blockIdx.x >> 1;
    const int half = blockIdx.x & 1;
    const int tid  = threadIdx.x;

    {   // coalesced image load: 768 float4 / 128 threads = 6 each
        const float4* src = reinterpret_cast<const float4*>(x + (size_t)n * (CIN * HH * WW));
        float4* dst = reinterpret_cast<float4*>(s_in);
        #pragma unroll
        for (int i = 0; i < 6; i++) dst[tid + i * 128] = src[tid + i * 128];
    }
    __syncthreads();

    const int warp = tid >> 5;
    const int lane = tid & 31;
    const int c0   = (half * 4 + warp) * 2;
    const int ch   = c0 + (lane >> 4);       // this lane's channel
    const int k    = lane & 15;              // column pair index (0..14 active)

    // per-lane duplicated weights {w,w} and bias
    u64 wd[27];
    #pragma unroll
    for (int t = 0; t < 27; t++) wd[t] = dup2(wgt[ch * 27 + t]);
    const u64 bd = dup2(bias[ch]);

    if (k == 15) return;   // lanes 15 and 31 idle (30 columns = 15 pairs)

    const float* base = s_in + 2 * k;        // [ci*1024 + row*32 + 2k]
    float* outp = out + ((size_t)n * COUT + ch) * (OH * OW) + 2 * k;

    // double-buffered row window: per ci, two aligned u64 pairs
    // q[ci][0] = {x[2k],x[2k+1]}, q[ci][1] = {x[2k+2],x[2k+3]}
    u64 qa[6], qb[6];
    u64 acc[3];            // acc[y % 3] = {out[y][2k], out[y][2k+1]}

    #pragma unroll
    for (int ci = 0; ci < CIN; ci++) {       // preload input row 0
        qa[ci * 2 + 0] = *reinterpret_cast<const u64*>(base + ci * 1024 + 0);
        qa[ci * 2 + 1] = *reinterpret_cast<const u64*>(base + ci * 1024 + 2);
    }

    #pragma unroll
    for (int r = 0; r < 32; r++) {
        // prefetch input row r+1 into the other buffer (full-row distance)
        if (r < 31) {
            #pragma unroll
            for (int ci = 0; ci < CIN; ci++) {
                const u64 v0 = *reinterpret_cast<const u64*>(base + ci * 1024 + (r + 1) * 32 + 0);
                const u64 v1 = *reinterpret_cast<const u64*>(base + ci * 1024 + (r + 1) * 32 + 2);
                if (r & 1) { qa[ci * 2 + 0] = v0; qa[ci * 2 + 1] = v1; }
                else       { qb[ci * 2 + 0] = v0; qb[ci * 2 + 1] = v1; }
            }
        }

        if (r <= 29) acc[r % 3] = bd;

        #pragma unroll
        for (int ci = 0; ci < CIN; ci++) {
            const u64 q0 = (r & 1) ? qb[ci * 2 + 0] : qa[ci * 2 + 0];
            const u64 q1 = (r & 1) ? qb[ci * 2 + 1] : qa[ci * 2 + 1];
            // middle pair {v1, v2}: extract halves (register-aliased MOVs) + 1 pack
            float d0, v1h, v2l, d1;
            upk2(q0, d0, v1h);
            upk2(q1, v2l, d1);
            const u64 pm = pk2(v1h, v2l);

            if (r >= 2) {
                acc[(r - 2) % 3] = fma2(q0, wd[ci * 9 + 6 + 0], acc[(r - 2) % 3]);
                acc[(r - 2) % 3] = fma2(pm, wd[ci * 9 + 6 + 1], acc[(r - 2) % 3]);
                acc[(r - 2) % 3] = fma2(q1, wd[ci * 9 + 6 + 2], acc[(r - 2) % 3]);
            }
            if (r >= 1 && r <= 30) {
                acc[(r - 1) % 3] = fma2(q0, wd[ci * 9 + 3 + 0], acc[(r - 1) % 3]);
                acc[(r - 1) % 3] = fma2(pm, wd[ci * 9 + 3 + 1], acc[(r - 1) % 3]);
                acc[(r - 1) % 3] = fma2(q1, wd[ci * 9 + 3 + 2], acc[(r - 1) % 3]);
            }
            if (r <= 29) {
                acc[r % 3] = fma2(q0, wd[ci * 9 + 0 + 0], acc[r % 3]);
                acc[r % 3] = fma2(pm, wd[ci * 9 + 0 + 1], acc[r % 3]);
                acc[r % 3] = fma2(q1, wd[ci * 9 + 0 + 2], acc[r % 3]);
            }
        }

        // output row y = r-2 complete: one STG.64 (two adjacent columns)
        if (r >= 2) {
            float v0, v1;
            upk2(acc[(r - 2) % 3], v0, v1);
            float2 st;
            st.x = hswish_relu(v0);
            st.y = hswish_relu(v1);
            *reinterpret_cast<float2*>(outp + (r - 2) * OW) = st;
        }
    }
}

extern "C" void kernel_launch(void* const* d_in, const int* in_sizes, int n_in,
                              void* d_out, int out_size) {
    const float* x = (const float*)d_in[0];
    const float* w = (const float*)d_in[1];
    const float* b = (const float*)d_in[2];
    float* out = (float*)d_out;

    const int N = in_sizes[0] / (CIN * HH * WW);   // 4096
    conv3x3_hswish_kernel<<<N * 2, 128>>>(x, w, b, out);
}